// round 2
// baseline (speedup 1.0000x reference)
#include <cuda_runtime.h>
#include <cuda_bf16.h>

#define HID 256
#define GAMMA_F 12.0f

// One warp per negative candidate. hr (head+rel) lives in registers:
// lane l holds hr[l*8 .. l*8+7] as two float4s. Tail row gathered as
// 2x float4 per lane (fully coalesced 1KB row read). Warp-shuffle reduce.
__global__ void __launch_bounds__(256, 8)
kge_transe_kernel(const float* __restrict__ ent,
                  const float* __restrict__ rel,
                  const int* __restrict__ pos,
                  const int* __restrict__ neg,
                  float* __restrict__ out,
                  int nneg)
{
    const int b    = blockIdx.y;
    const int lane = threadIdx.x & 31;
    const int warp = threadIdx.x >> 5;

    // head + relation for this batch row -> registers
    const int hidx = pos[b * 3 + 0];
    const int ridx = pos[b * 3 + 1];
    const float4* hrow = reinterpret_cast<const float4*>(ent + (long long)hidx * HID);
    const float4* rrow = reinterpret_cast<const float4*>(rel + (long long)ridx * HID);

    float4 h0 = hrow[lane * 2 + 0];
    float4 h1 = hrow[lane * 2 + 1];
    float4 r0 = rrow[lane * 2 + 0];
    float4 r1 = rrow[lane * 2 + 1];

    float4 a0, a1;
    a0.x = h0.x + r0.x;  a0.y = h0.y + r0.y;
    a0.z = h0.z + r0.z;  a0.w = h0.w + r0.w;
    a1.x = h1.x + r1.x;  a1.y = h1.y + r1.y;
    a1.z = h1.z + r1.z;  a1.w = h1.w + r1.w;

    const int* nrow = neg + (long long)b * nneg;
    float*     orow = out + (long long)b * nneg;

    const int gwarp  = blockIdx.x * (blockDim.x >> 5) + warp;
    const int nwarps = gridDim.x * (blockDim.x >> 5);

    for (int n = gwarp; n < nneg; n += nwarps) {
        const int t = nrow[n];  // broadcast load (all lanes same addr)
        const float4* trow = reinterpret_cast<const float4*>(ent + (long long)t * HID);
        const float4 t0 = trow[lane * 2 + 0];
        const float4 t1 = trow[lane * 2 + 1];

        float s = fabsf(a0.x - t0.x) + fabsf(a0.y - t0.y)
                + fabsf(a0.z - t0.z) + fabsf(a0.w - t0.w)
                + fabsf(a1.x - t1.x) + fabsf(a1.y - t1.y)
                + fabsf(a1.z - t1.z) + fabsf(a1.w - t1.w);

        // butterfly reduction across the warp
        s += __shfl_xor_sync(0xFFFFFFFFu, s, 16);
        s += __shfl_xor_sync(0xFFFFFFFFu, s, 8);
        s += __shfl_xor_sync(0xFFFFFFFFu, s, 4);
        s += __shfl_xor_sync(0xFFFFFFFFu, s, 2);
        s += __shfl_xor_sync(0xFFFFFFFFu, s, 1);

        if (lane == 0) orow[n] = GAMMA_F - s;
    }
}

extern "C" void kernel_launch(void* const* d_in, const int* in_sizes, int n_in,
                              void* d_out, int out_size)
{
    const float* ent = (const float*)d_in[0];  // [NENTITY, 256] f32
    const float* rel = (const float*)d_in[1];  // [NRELATION, 256] f32
    const int*   pos = (const int*)d_in[2];    // [B, 3] int32 (JAX x64 disabled)
    const int*   neg = (const int*)d_in[3];    // [B, N] int32
    float*       out = (float*)d_out;          // [B, N] f32

    const int batch = in_sizes[2] / 3;
    const int nneg  = in_sizes[3] / batch;

    dim3 grid(148, batch);
    dim3 block(256);
    kge_transe_kernel<<<grid, block>>>(ent, rel, pos, neg, out, nneg);
}

// round 3
// speedup vs baseline: 1.9764x; 1.9764x over previous
#include <cuda_runtime.h>
#include <cuda_bf16.h>

#define HID 256
#define GAMMA_F 12.0f
#define BATCH 8

// Scratch: S[e*8 + b] = gamma - L1dist(hr_b, ent_e). 100000*8 floats = 3.2MB.
__device__ float g_scores[BATCH * 100000];

// ---------------------------------------------------------------------------
// Phase 1: stream entity table once, score all 8 (head+rel) vectors per row.
// Warp per row. hr[8][8] in registers (lane covers dims lane*8..lane*8+7).
// Folding reduction: 9 shuffles/row; lane 4b ends with sum for batch b.
// ---------------------------------------------------------------------------
__global__ void __launch_bounds__(256, 2)
score_all_kernel(const float* __restrict__ ent,
                 const float* __restrict__ rel,
                 const int*   __restrict__ pos,
                 float*       __restrict__ scores,
                 int ne)
{
    const int lane = threadIdx.x & 31;
    const int warp = threadIdx.x >> 5;

    // Build hr = head + relation, 8 floats per lane per batch -> 64 regs.
    float hr[BATCH][8];
#pragma unroll
    for (int b = 0; b < BATCH; b++) {
        const int hidx = pos[b * 3 + 0];
        const int ridx = pos[b * 3 + 1];
        const float4* h4 = reinterpret_cast<const float4*>(ent + (size_t)hidx * HID);
        const float4* r4 = reinterpret_cast<const float4*>(rel + (size_t)ridx * HID);
        float4 h0 = h4[lane * 2], h1 = h4[lane * 2 + 1];
        float4 r0 = r4[lane * 2], r1 = r4[lane * 2 + 1];
        hr[b][0] = h0.x + r0.x;  hr[b][1] = h0.y + r0.y;
        hr[b][2] = h0.z + r0.z;  hr[b][3] = h0.w + r0.w;
        hr[b][4] = h1.x + r1.x;  hr[b][5] = h1.y + r1.y;
        hr[b][6] = h1.z + r1.z;  hr[b][7] = h1.w + r1.w;
    }

    const bool hi16 = (lane & 16) != 0;
    const bool hi8  = (lane & 8)  != 0;
    const bool hi4  = (lane & 4)  != 0;

    const int gw = blockIdx.x * (blockDim.x >> 5) + warp;
    const int nw = gridDim.x * (blockDim.x >> 5);

    int row = gw;
    float4 e0, e1, p0, p1;
    if (row < ne) {
        const float4* er = reinterpret_cast<const float4*>(ent + (size_t)row * HID);
        e0 = er[lane * 2];  e1 = er[lane * 2 + 1];
    }

    while (row < ne) {
        const int nxt = row + nw;
        if (nxt < ne) {  // prefetch next row
            const float4* pr = reinterpret_cast<const float4*>(ent + (size_t)nxt * HID);
            p0 = pr[lane * 2];  p1 = pr[lane * 2 + 1];
        }

        const float e[8] = { e0.x, e0.y, e0.z, e0.w, e1.x, e1.y, e1.z, e1.w };

        float v[BATCH];
#pragma unroll
        for (int b = 0; b < BATCH; b++) {
            float s = 0.0f;
#pragma unroll
            for (int j = 0; j < 8; j++) {
                const float d = __fmaf_rn(e[j], -1.0f, hr[b][j]);   // FFMA-imm
                s = __fmaf_rn(fabsf(d), 1.0f, s);                   // FFMA-imm
            }
            v[b] = s;
        }

        // Folding reduction: after each stage, half the values, batches split
        // across lane groups. End: lane group l>>2 == b holds sum for batch b.
        // Stage xor16: 8 -> 4 values
#pragma unroll
        for (int j = 0; j < 4; j++) {
            const float send = hi16 ? v[j] : v[j + 4];
            const float recv = __shfl_xor_sync(0xFFFFFFFFu, send, 16);
            v[j] = (hi16 ? v[j + 4] : v[j]) + recv;
        }
        // Stage xor8: 4 -> 2
#pragma unroll
        for (int j = 0; j < 2; j++) {
            const float send = hi8 ? v[j] : v[j + 2];
            const float recv = __shfl_xor_sync(0xFFFFFFFFu, send, 8);
            v[j] = (hi8 ? v[j + 2] : v[j]) + recv;
        }
        // Stage xor4: 2 -> 1
        {
            const float send = hi4 ? v[0] : v[1];
            const float recv = __shfl_xor_sync(0xFFFFFFFFu, send, 4);
            v[0] = (hi4 ? v[1] : v[0]) + recv;
        }
        // Final: sum the 4 copies within each 4-lane group.
        v[0] += __shfl_xor_sync(0xFFFFFFFFu, v[0], 2);
        v[0] += __shfl_xor_sync(0xFFFFFFFFu, v[0], 1);

        // Batch id for this lane group = lane>>2; lanes with lane&3==0 write.
        if ((lane & 3) == 0)
            scores[(size_t)row * BATCH + (lane >> 2)] = GAMMA_F - v[0];

        e0 = p0;  e1 = p1;
        row = nxt;
    }
}

// ---------------------------------------------------------------------------
// Phase 2: out[b][n] = scores[neg[b][n]*8 + b]. 4 elements per thread.
// ---------------------------------------------------------------------------
__global__ void __launch_bounds__(256)
gather_kernel(const float* __restrict__ scores,
              const int*   __restrict__ neg,
              float*       __restrict__ out,
              int nneg)
{
    const int b = blockIdx.y;
    const int t = blockIdx.x * blockDim.x + threadIdx.x;
    const int n4 = nneg >> 2;              // nneg divisible by 4
    if (t >= n4) return;

    const int4 idx = reinterpret_cast<const int4*>(neg + (size_t)b * nneg)[t];
    float4 r;
    r.x = scores[(size_t)idx.x * BATCH + b];
    r.y = scores[(size_t)idx.y * BATCH + b];
    r.z = scores[(size_t)idx.z * BATCH + b];
    r.w = scores[(size_t)idx.w * BATCH + b];
    reinterpret_cast<float4*>(out + (size_t)b * nneg)[t] = r;
}

extern "C" void kernel_launch(void* const* d_in, const int* in_sizes, int n_in,
                              void* d_out, int out_size)
{
    const float* ent = (const float*)d_in[0];  // [NE, 256] f32
    const float* rel = (const float*)d_in[1];  // [NR, 256] f32
    const int*   pos = (const int*)d_in[2];    // [B, 3] int32
    const int*   neg = (const int*)d_in[3];    // [B, N] int32
    float*       out = (float*)d_out;          // [B, N] f32

    const int batch = in_sizes[2] / 3;         // 8
    const int nneg  = in_sizes[3] / batch;     // 100000
    const int ne    = in_sizes[0] / HID;       // 100000

    float* scores;
    cudaGetSymbolAddress((void**)&scores, g_scores);

    // Phase 1: 296 blocks x 256 threads (2 blocks/SM resident, one wave).
    score_all_kernel<<<296, 256>>>(ent, rel, pos, scores, ne);

    // Phase 2: gather
    dim3 g2((nneg / 4 + 255) / 256, batch);
    gather_kernel<<<g2, 256>>>(scores, neg, out, nneg);
}